// round 15
// baseline (speedup 1.0000x reference)
#include <cuda_runtime.h>
#include <cuda_fp16.h>
#include <cstdint>

// ---------------------------------------------------------------------------
// SymmetricContraction via monomial GEMM (fp16 in / fp32 accum mma.m16n8k16).
// out[b,c] = sum_k W3[k]*Q3[k] + U2/U1 scalar terms
//   Q3[b,c,k] = sum_T A[T,k] * m[b,c,T],  m = x_a x_b x_c over sorted triples
// Quad-even (a,b) runs -> each lane's 4 A-columns share one (a,b) product.
// A-fragments generated directly in registers; barrier-free main loop.
// ---------------------------------------------------------------------------

#define CC   128
#define LL   16
#define EE   10
#define PP3  23
#define PP2  4
#define NU3  (16*16*16*23)   // 94208
#define MAXK 1248            // sorted triples + quad padding (bound 1240), mult 16
#define NQ   (MAXK/4)        // 312 quads
#define NPAD 24              // GEMM N: 23 paths + 1 zero col
#define NNODES 3
#define THREADS (NNODES*128)

// ---- device globals (no allocation allowed) ----
__device__ float          g_Af[MAXK][NPAD];   // fp32 A accumulation
__device__ __half         g_AhT[NPAD][MAXK];  // A transposed, fp16
__device__ uint2          g_specq[NQ + 8];    // quad spec: a|b<<8|c0<<16|c1<<24, c2|c3<<8
__device__ unsigned short g_cellid[4096];     // sorted-cell -> physical slot
__device__ uint2          g_e2[1040];         // U2: (w|x<<8|k<<16, f32 v)
__device__ unsigned       g_K;                // padded K
__device__ unsigned       g_n2;

// ---------------------------------------------------------------------------
__device__ __forceinline__ int block_exscan_1024(int cnt, int t, int* warp_sums, int* total)
{
    __syncthreads();
    const int lane = t & 31, wid = t >> 5;
    int inc = cnt;
#pragma unroll
    for (int d = 1; d < 32; d <<= 1) {
        int n = __shfl_up_sync(0xffffffffu, inc, d);
        if (lane >= d) inc += n;
    }
    if (lane == 31) warp_sums[wid] = inc;
    __syncthreads();
    if (wid == 0) {
        int v = warp_sums[lane];
#pragma unroll
        for (int d = 1; d < 32; d <<= 1) {
            int n = __shfl_up_sync(0xffffffffu, v, d);
            if (lane >= d) v += n;
        }
        warp_sums[lane] = v;
    }
    __syncthreads();
    *total = warp_sums[31];
    return inc - cnt + (wid ? warp_sums[wid - 1] : 0);
}

__device__ __forceinline__ void sort3(int& a, int& b, int& c)
{
    int t;
    if (a > b) { t = a; a = b; b = t; }
    if (b > c) { t = b; b = c; c = t; }
    if (a > b) { t = a; a = b; b = t; }
}

// slot of member mm of global quad qg: chunk kb=16*(qg>>2), col 2*(qg&3)+(mm&1)+8*(mm>>1)
__device__ __forceinline__ int quad_slot(int qg, int mm)
{
    return 16 * (qg >> 2) + 2 * (qg & 3) + (mm & 1) + 8 * (mm >> 1);
}

// ---------------------------------------------------------------------------
// b0: single block. used3 bitmap -> quad-even slotting -> specq/cellid. U2 list.
// ---------------------------------------------------------------------------
__global__ __launch_bounds__(1024)
void build_b0(const float* __restrict__ U3, const float* __restrict__ U2)
{
    __shared__ int           warp_sums[32];
    __shared__ unsigned char used3[4096];
    const int t = threadIdx.x;

    // default quad spec: a=0,b=0,c=15 (valid rows, zero A rows)
    for (int idx = t; idx < NQ + 8; idx += 1024)
        g_specq[idx] = make_uint2((15u << 16) | (15u << 24), 15u | (15u << 8));
#pragma unroll
    for (int j = 0; j < 4; ++j) used3[t * 4 + j] = 0;
    __syncthreads();

    // mark used sorted triples
    const int base = t * 92;
    const int w  = t >> 6;
    const int x2 = (t >> 2) & 15;
#pragma unroll
    for (int g = 0; g < 4; ++g) {
        const int i = (t & 3) * 4 + g;
        for (int k = 0; k < PP3; ++k) {
            if (U3[base + g * PP3 + k] != 0.f) {
                int a = w, b = x2, c = i;
                sort3(a, b, c);
                used3[a * 256 + b * 16 + c] = 1;
            }
        }
    }
    __syncthreads();

    // quad-even slotting: pair (a,b) with a<=b owns ceil(cnt/4) quads
    int a = t >> 4, b = t & 15;
    int cnt = 0;
    if (t < 256 && a <= b)
        for (int c = b; c < 16; ++c) cnt += used3[a * 256 + b * 16 + c];
    int quads = (cnt + 3) >> 2;
    int totalq;
    int qbase = block_exscan_1024((t < 256) ? quads : 0, t, warp_sums, &totalq);
    if (t < 256 && cnt > 0) {
        int m = 0, qg = qbase;
        uint32_t cs0 = 15, cs1 = 15, cs2 = 15, cs3 = 15;
        for (int c = b; c < 16; ++c) {
            const int cell = a * 256 + b * 16 + c;
            if (used3[cell]) {
                const int mm = m & 3;
                if (mm == 0) cs0 = c; else if (mm == 1) cs1 = c;
                else if (mm == 2) cs2 = c; else cs3 = c;
                g_cellid[cell] = (unsigned short)quad_slot(qg, mm);
                ++m;
                if (mm == 3) {
                    g_specq[qg] = make_uint2((uint32_t)a | ((uint32_t)b << 8) | (cs0 << 16) | (cs1 << 24),
                                             cs2 | (cs3 << 8));
                    ++qg;
                    cs0 = cs1 = cs2 = cs3 = 15;
                }
            }
        }
        if (m & 3)
            g_specq[qg] = make_uint2((uint32_t)a | ((uint32_t)b << 8) | (cs0 << 16) | (cs1 << 24),
                                     cs2 | (cs3 << 8));
    }
    if (t == 0) g_K = (unsigned)((4 * totalq + 15) & ~15);

    // ---- U2 list ----
    int cnt2 = 0;
    if (t < 256) {
#pragma unroll
        for (int k = 0; k < PP2; ++k) cnt2 += (U2[t * PP2 + k] != 0.f);
    }
    int total2;
    int p2 = block_exscan_1024(cnt2, t, warp_sums, &total2);
    if (t < 256) {
        const uint32_t wx = (uint32_t)(t >> 4) | ((uint32_t)(t & 15) << 8);
        for (int k = 0; k < PP2; ++k) {
            float v = U2[t * PP2 + k];
            if (v != 0.f) {
                g_e2[p2] = make_uint2(wx | ((uint32_t)k << 16), __float_as_uint(v));
                ++p2;
            }
        }
    }
    if (t == 0) g_n2 = (unsigned)total2;
}

// b1: zero A accumulator (grid-wide)
__global__ void build_b1()
{
    int i = blockIdx.x * blockDim.x + threadIdx.x;
    if (i < MAXK * NPAD) (&g_Af[0][0])[i] = 0.f;
}

// b2: accumulate A (grid-wide, one thread per U3 element)
__global__ void build_b2(const float* __restrict__ U3)
{
    int i = blockIdx.x * blockDim.x + threadIdx.x;
    if (i >= NU3) return;
    float v = U3[i];
    if (v == 0.f) return;
    int k = i % PP3;
    int r = i / PP3;
    int a = r >> 8, b = (r >> 4) & 15, c = r & 15;
    sort3(a, b, c);
    atomicAdd(&g_Af[g_cellid[a * 256 + b * 16 + c]][k], v);
}

// b3a/b3b: convert to transposed fp16 (split for ncu launch alignment)
#define B3HALF ((NPAD * MAXK) / 2)
__global__ void build_b3a()
{
    int i = blockIdx.x * blockDim.x + threadIdx.x;
    if (i >= B3HALF) return;
    int n = i / MAXK, m = i % MAXK;
    g_AhT[n][m] = __float2half(g_Af[m][n]);
}
__global__ void build_b3b()
{
    int i = B3HALF + blockIdx.x * blockDim.x + threadIdx.x;
    if (i >= NPAD * MAXK) return;
    int n = i / MAXK, m = i % MAXK;
    g_AhT[n][m] = __float2half(g_Af[m][n]);
}

// ---------------------------------------------------------------------------
#define MMA16816(d0,d1,d2,d3,a0,a1,a2,a3,b0,b1)                         \
    asm volatile("mma.sync.aligned.m16n8k16.row.col.f32.f16.f16.f32 "   \
        "{%0,%1,%2,%3}, {%4,%5,%6,%7}, {%8,%9}, {%0,%1,%2,%3};"         \
        : "+f"(d0), "+f"(d1), "+f"(d2), "+f"(d3)                        \
        : "r"(a0), "r"(a1), "r"(a2), "r"(a3), "r"(b0), "r"(b1))

__device__ __forceinline__ __half2 u2h2(uint32_t u) { return *reinterpret_cast<__half2*>(&u); }
__device__ __forceinline__ uint32_t h2u(__half2 h) { return *reinterpret_cast<uint32_t*>(&h); }

// ---------------------------------------------------------------------------
// smem layout (bytes), block = 3 nodes x 128 threads
// X paired: row l = 64 half2; entry e=8q+r holds half2(x[16q+r], x[16q+r+8]).
// AhT row stride 2512 B (628 words ≡ 12 mod 32 -> B loads conflict-free).
// ---------------------------------------------------------------------------
#define AHT_ROW   2512                        // MAXK*2 (=2496) + 16 pad
#define OFF_AHT   0
#define OFF_SPEC  (NPAD * AHT_ROW)            // 60288
#define OFF_NODE  (OFF_SPEC + NQ * 8)         // 62784
#define XH_ROW    272                         // 64 half2 (256B) + 16 pad
#define W3H_ROW   264                         // 128 fp16 + 8 pad
#define NB_XH     0
#define NB_W3     (NB_XH + LL * XH_ROW)       // 4352
#define NB_W2     (NB_W3 + NPAD * W3H_ROW)    // 10688
#define NB_W1     (NB_W2 + PP2 * 256)         // 11712
#define NB_OUT    (NB_W1 + 512)               // 12224
#define NODE_BYTES (NB_OUT + 512)             // 12736
#define SH_BYTES  (OFF_NODE + NNODES * NODE_BYTES)  // 100992

__global__ __launch_bounds__(THREADS, 2)
void sym_gemm_kernel(const float* __restrict__ x,
                     const float* __restrict__ y,
                     const float* __restrict__ w3,
                     const float* __restrict__ w2,
                     const float* __restrict__ w1,
                     const float* __restrict__ U1,
                     float* __restrict__ out,
                     int B)
{
    extern __shared__ char sm[];
    const int tid  = threadIdx.x;
    const int node = tid >> 7;
    const int wt   = tid & 127;               // channel for setup phases
    const int b    = blockIdx.x * NNODES + node;
    const bool valid = (b < B);

    char* nb  = sm + OFF_NODE + node * NODE_BYTES;
    char* xh  = nb + NB_XH;
    char* w3h = nb + NB_W3;
    char* w2h = nb + NB_W2;
    float* w1f  = reinterpret_cast<float*>(nb + NB_W1);
    float* outs = reinterpret_cast<float*>(nb + NB_OUT);

    const int KP = (int)g_K;
    const int n2 = (int)g_n2;

    // ---- copy AhT + quad spec into smem (all threads) ----
    for (int idx = tid; idx < NPAD * 156; idx += THREADS) {
        const int r = idx / 156, j = idx % 156;
        *reinterpret_cast<uint4*>(sm + OFF_AHT + r * AHT_ROW + j * 16) =
            *reinterpret_cast<const uint4*>(reinterpret_cast<const char*>(&g_AhT[0][0]) + r * (MAXK * 2) + j * 16);
    }
    for (int idx = tid; idx < NQ; idx += THREADS)
        *reinterpret_cast<uint2*>(sm + OFF_SPEC + idx * 8) = g_specq[idx];

    // ---- stage x as PAIRED fp16: entry e = 8*(wt>>4)+(wt&7), half h = (wt>>3)&1
    const int xe = 8 * (wt >> 4) + (wt & 7);
    const int xho = (wt >> 3) & 1;
    if (valid) {
        const float4* xp = reinterpret_cast<const float4*>(x + ((size_t)b * CC + wt) * LL);
#pragma unroll
        for (int q = 0; q < 4; ++q) {
            float4 r = xp[q];
            *reinterpret_cast<__half*>(xh + (4 * q + 0) * XH_ROW + xe * 4 + xho * 2) = __float2half(r.x);
            *reinterpret_cast<__half*>(xh + (4 * q + 1) * XH_ROW + xe * 4 + xho * 2) = __float2half(r.y);
            *reinterpret_cast<__half*>(xh + (4 * q + 2) * XH_ROW + xe * 4 + xho * 2) = __float2half(r.z);
            *reinterpret_cast<__half*>(xh + (4 * q + 3) * XH_ROW + xe * 4 + xho * 2) = __float2half(r.w);
        }
    } else {
#pragma unroll
        for (int l = 0; l < LL; ++l)
            *reinterpret_cast<__half*>(xh + l * XH_ROW + xe * 4 + xho * 2) = __float2half(0.f);
    }

    // ---- effective weights ----
    float yr[EE];
#pragma unroll
    for (int e = 0; e < EE; ++e) yr[e] = valid ? __ldg(y + (size_t)b * EE + e) : 0.f;

#pragma unroll
    for (int k = 0; k < PP3; ++k) {
        float s = 0.f;
#pragma unroll
        for (int e = 0; e < EE; ++e)
            s = fmaf(yr[e], __ldg(w3 + (size_t)(e * PP3 + k) * CC + wt), s);
        *reinterpret_cast<__half*>(w3h + k * W3H_ROW + wt * 2) = __float2half(s);
    }
    *reinterpret_cast<__half*>(w3h + 23 * W3H_ROW + wt * 2) = __float2half(0.f);  // pad col
#pragma unroll
    for (int k = 0; k < PP2; ++k) {
        float s = 0.f;
#pragma unroll
        for (int e = 0; e < EE; ++e)
            s = fmaf(yr[e], __ldg(w2 + (size_t)(e * PP2 + k) * CC + wt), s);
        *reinterpret_cast<__half*>(w2h + k * 256 + wt * 2) = __float2half(s);
    }
    {
        float s = 0.f;
#pragma unroll
        for (int e = 0; e < EE; ++e)
            s = fmaf(yr[e], __ldg(w1 + (size_t)e * CC + wt), s);
        w1f[wt] = s;
    }
    __syncthreads();   // x (written by other threads' channels) + tables ready

    // ---- U2 + U1 scalar terms for channel wt ----
    {
        float o = 0.f;
        for (int e = 0; e < n2; ++e) {
            uint2 E = __ldg(&g_e2[e]);
            const int ww = E.x & 255, xx = (E.x >> 8) & 255, kk = E.x >> 16;
            float xw = __half2float(*reinterpret_cast<const __half*>(xh + ww * XH_ROW + xe * 4 + xho * 2))
                     * __half2float(*reinterpret_cast<const __half*>(xh + xx * XH_ROW + xe * 4 + xho * 2));
            float wv = __half2float(*reinterpret_cast<const __half*>(w2h + kk * 256 + wt * 2));
            o = fmaf(__uint_as_float(E.y) * wv, xw, o);
        }
        float d = 0.f;
#pragma unroll
        for (int l = 0; l < LL; ++l)
            d = fmaf(__ldg(U1 + l),
                     __half2float(*reinterpret_cast<const __half*>(xh + l * XH_ROW + xe * 4 + xho * 2)), d);
        o = fmaf(w1f[wt], d, o);
        outs[wt] = o;
    }

    // ---- GEMM main loop: barrier-free, quad-shared A gen ----
    const int lane = tid & 31;
    const int wm   = (tid >> 5) & 3;          // warp within node
    const int g4   = lane >> 2;
    const int t4   = lane & 3;

    // per-lane x column base for each m-tile: entry = 8*(2*wm+mt) + g4
    const char* xc0 = xh + (8 * (2 * wm + 0) + g4) * 4;
    const char* xc1 = xh + (8 * (2 * wm + 1) + g4) * 4;
    const uint2* spq = reinterpret_cast<const uint2*>(sm + OFF_SPEC);
    const char* bb = sm + OFF_AHT + g4 * AHT_ROW + t4 * 4;

    float acc[2][3][4];
#pragma unroll
    for (int mt = 0; mt < 2; ++mt)
#pragma unroll
        for (int nt = 0; nt < 3; ++nt)
#pragma unroll
            for (int q = 0; q < 4; ++q) acc[mt][nt][q] = 0.f;

    const int nchunks = KP >> 4;
    for (int c = 0; c < nchunks; ++c) {
        const int kb = c * 16;
        uint2 sp = spq[4 * c + t4];           // this lane's quad
        const uint32_t ra  = sp.x & 255u,  rb  = (sp.x >> 8) & 255u;
        const uint32_t rc0 = (sp.x >> 16) & 255u, rc1 = sp.x >> 24;
        const uint32_t rc2 = sp.y & 255u,  rc3 = (sp.y >> 8) & 255u;

        uint32_t afr[2][4];
#pragma unroll
        for (int mt = 0; mt < 2; ++mt) {
            const char* xc = mt ? xc1 : xc0;
            __half2 xa = u2h2(*reinterpret_cast<const uint32_t*>(xc + ra * XH_ROW));
            __half2 xb = u2h2(*reinterpret_cast<const uint32_t*>(xc + rb * XH_ROW));
            __half2 ab = __hmul2(xa, xb);
            uint32_t p0 = h2u(__hmul2(ab, u2h2(*reinterpret_cast<const uint32_t*>(xc + rc0 * XH_ROW))));
            uint32_t p1 = h2u(__hmul2(ab, u2h2(*reinterpret_cast<const uint32_t*>(xc + rc1 * XH_ROW))));
            uint32_t p2 = h2u(__hmul2(ab, u2h2(*reinterpret_cast<const uint32_t*>(xc + rc2 * XH_ROW))));
            uint32_t p3 = h2u(__hmul2(ab, u2h2(*reinterpret_cast<const uint32_t*>(xc + rc3 * XH_ROW))));
            afr[mt][0] = __byte_perm(p0, p1, 0x5410);  // rows g4,   cols (2t4, 2t4+1)
            afr[mt][1] = __byte_perm(p0, p1, 0x7632);  // rows g4+8, cols (2t4, 2t4+1)
            afr[mt][2] = __byte_perm(p2, p3, 0x5410);  // rows g4,   cols (2t4+8, 2t4+9)
            afr[mt][3] = __byte_perm(p2, p3, 0x7632);  // rows g4+8, cols (2t4+8, 2t4+9)
        }

        // B fragments + mma
#pragma unroll
        for (int nt = 0; nt < 3; ++nt) {
            const char* bp = bb + nt * (8 * AHT_ROW) + kb * 2;
            uint32_t b0 = *reinterpret_cast<const uint32_t*>(bp);
            uint32_t b1 = *reinterpret_cast<const uint32_t*>(bp + 16);
            MMA16816(acc[0][nt][0], acc[0][nt][1], acc[0][nt][2], acc[0][nt][3],
                     afr[0][0], afr[0][1], afr[0][2], afr[0][3], b0, b1);
            MMA16816(acc[1][nt][0], acc[1][nt][1], acc[1][nt][2], acc[1][nt][3],
                     afr[1][0], afr[1][1], afr[1][2], afr[1][3], b0, b1);
        }
    }

    // ---- epilogue: out[ch] = outs[ch] + sum_k W3[k][ch] * Q[ch][k] ----
#pragma unroll
    for (int mt = 0; mt < 2; ++mt) {
#pragma unroll
        for (int h = 0; h < 2; ++h) {
            const int ch = wm * 32 + mt * 16 + g4 + h * 8;
            float S = 0.f;
#pragma unroll
            for (int nt = 0; nt < 3; ++nt) {
                const int k0 = nt * 8 + 2 * t4;
                float wv0 = __half2float(*reinterpret_cast<const __half*>(w3h + k0 * W3H_ROW + ch * 2));
                float wv1 = __half2float(*reinterpret_cast<const __half*>(w3h + (k0 + 1) * W3H_ROW + ch * 2));
                S = fmaf(acc[mt][nt][h * 2 + 0], wv0, S);
                S = fmaf(acc[mt][nt][h * 2 + 1], wv1, S);
            }
            S += __shfl_xor_sync(0xffffffffu, S, 1);
            S += __shfl_xor_sync(0xffffffffu, S, 2);
            if (t4 == 0 && valid)
                out[(size_t)b * CC + ch] = S + outs[ch];
        }
    }
}

// ---------------------------------------------------------------------------
extern "C" void kernel_launch(void* const* d_in, const int* in_sizes, int n_in,
                              void* d_out, int out_size)
{
    const float* x  = (const float*)d_in[0];   // [B,C,L]
    const float* y  = (const float*)d_in[1];   // [B,E]
    const float* U3 = (const float*)d_in[2];   // [16,16,16,23]
    const float* U2 = (const float*)d_in[3];   // [16,16,4]
    const float* U1 = (const float*)d_in[4];   // [16,1]
    const float* w3 = (const float*)d_in[5];   // [10,23,128]
    const float* w2 = (const float*)d_in[6];   // [10,4,128]
    const float* w1 = (const float*)d_in[7];   // [10,1,128]
    float* out = (float*)d_out;

    const int B = in_sizes[0] / (CC * LL);

    build_b0<<<1, 1024>>>(U3, U2);
    build_b1<<<(MAXK * NPAD + 255) / 256, 256>>>();
    build_b2<<<(NU3 + 255) / 256, 256>>>(U3);
    build_b3a<<<(B3HALF + 255) / 256, 256>>>();
    build_b3b<<<(B3HALF + 255) / 256, 256>>>();

    cudaFuncSetAttribute(sym_gemm_kernel,
                         cudaFuncAttributeMaxDynamicSharedMemorySize, SH_BYTES);
    const int grid = (B + NNODES - 1) / NNODES;
    sym_gemm_kernel<<<grid, THREADS, SH_BYTES>>>(x, y, w3, w2, w1, U1, out, B);
}

// round 16
// speedup vs baseline: 1.1334x; 1.1334x over previous
#include <cuda_runtime.h>
#include <cuda_fp16.h>
#include <cstdint>

// ---------------------------------------------------------------------------
// SymmetricContraction via monomial GEMM (fp16 in / fp32 accum mma.m16n8k16).
// out[b,c] = sum_k W3[k]*Q3[k] + U2/U1 scalar terms
//   Q3[b,c,k] = sum_T A[T,k] * m[b,c,T],  m = x_a x_b x_c over sorted triples
// Pair-even runs (K<=960). A-fragments generated in registers from a
// 4-replica X smem layout (one replica per t4 group -> provably conflict-free
// x-gather). B operand precomputed as fragment-major global table (L1-hot,
// fully coalesced LDG). Barrier-free main loop.
// ---------------------------------------------------------------------------

#define CC   128
#define LL   16
#define EE   10
#define PP3  23
#define PP2  4
#define NU3  (16*16*16*23)   // 94208
#define MAXK 960             // sorted triples + pair padding (bound 952)
#define NCHUNK (MAXK/16)     // 60
#define NPAD 24              // GEMM N: 23 paths + 1 zero col
#define NNODES 3
#define THREADS (NNODES*128)

// ---- device globals (no allocation allowed) ----
__device__ float          g_Af[MAXK][NPAD];        // fp32 A accumulation
__device__ uint32_t       g_Bf[NCHUNK*3*2*32];     // fragment-major B (fp16x2)
__device__ uint32_t       g_spec[MAXK];            // a | b<<8 | c<<16
__device__ unsigned short g_cellid[4096];          // sorted-cell -> slot
__device__ uint2          g_e2[1040];              // U2: (w|x<<8|k<<16, f32 v)
__device__ unsigned       g_K;                     // padded K
__device__ unsigned       g_n2;

// ---------------------------------------------------------------------------
__device__ __forceinline__ int block_exscan_1024(int cnt, int t, int* warp_sums, int* total)
{
    __syncthreads();
    const int lane = t & 31, wid = t >> 5;
    int inc = cnt;
#pragma unroll
    for (int d = 1; d < 32; d <<= 1) {
        int n = __shfl_up_sync(0xffffffffu, inc, d);
        if (lane >= d) inc += n;
    }
    if (lane == 31) warp_sums[wid] = inc;
    __syncthreads();
    if (wid == 0) {
        int v = warp_sums[lane];
#pragma unroll
        for (int d = 1; d < 32; d <<= 1) {
            int n = __shfl_up_sync(0xffffffffu, v, d);
            if (lane >= d) v += n;
        }
        warp_sums[lane] = v;
    }
    __syncthreads();
    *total = warp_sums[31];
    return inc - cnt + (wid ? warp_sums[wid - 1] : 0);
}

__device__ __forceinline__ void sort3(int& a, int& b, int& c)
{
    int t;
    if (a > b) { t = a; a = b; b = t; }
    if (b > c) { t = b; b = c; c = t; }
    if (a > b) { t = a; a = b; b = t; }
}

// ---------------------------------------------------------------------------
// b0: single block. used3 bitmap -> pair-even slotting -> spec/cellid. U2 list.
// (identical to the proven R14 build)
// ---------------------------------------------------------------------------
__global__ __launch_bounds__(1024)
void build_b0(const float* __restrict__ U3, const float* __restrict__ U2)
{
    __shared__ int           warp_sums[32];
    __shared__ unsigned char used3[4096];
    const int t = threadIdx.x;

    for (int idx = t; idx < MAXK; idx += 1024) g_spec[idx] = 0u;
#pragma unroll
    for (int j = 0; j < 4; ++j) used3[t * 4 + j] = 0;
    __syncthreads();

    const int base = t * 92;
    const int w  = t >> 6;
    const int x2 = (t >> 2) & 15;
#pragma unroll
    for (int g = 0; g < 4; ++g) {
        const int i = (t & 3) * 4 + g;
        for (int k = 0; k < PP3; ++k) {
            if (U3[base + g * PP3 + k] != 0.f) {
                int a = w, b = x2, c = i;
                sort3(a, b, c);
                used3[a * 256 + b * 16 + c] = 1;
            }
        }
    }
    __syncthreads();

    // pair-even slotting: pair (a,b) with a<=b owns even # of slots
    int a = t >> 4, b = t & 15;
    int cnt = 0;
    if (t < 256 && a <= b)
        for (int c = b; c < 16; ++c) cnt += used3[a * 256 + b * 16 + c];
    int slots = (cnt + 1) & ~1;
    int total;
    int basep = block_exscan_1024((t < 256) ? slots : 0, t, warp_sums, &total);
    if (t < 256 && cnt > 0) {
        int pos = basep;
        for (int c = b; c < 16; ++c) {
            const int cell = a * 256 + b * 16 + c;
            if (used3[cell]) {
                g_cellid[cell] = (unsigned short)pos;
                g_spec[pos] = (uint32_t)a | ((uint32_t)b << 8) | ((uint32_t)c << 16);
                ++pos;
            }
        }
        if (cnt & 1)   // dummy slot: same (a,b), A row stays zero
            g_spec[pos] = (uint32_t)a | ((uint32_t)b << 8) | (15u << 16);
    }
    if (t == 0) g_K = (unsigned)((total + 15) & ~15);

    // ---- U2 list ----
    int cnt2 = 0;
    if (t < 256) {
#pragma unroll
        for (int k = 0; k < PP2; ++k) cnt2 += (U2[t * PP2 + k] != 0.f);
    }
    int total2;
    int p2 = block_exscan_1024(cnt2, t, warp_sums, &total2);
    if (t < 256) {
        const uint32_t wx = (uint32_t)(t >> 4) | ((uint32_t)(t & 15) << 8);
        for (int k = 0; k < PP2; ++k) {
            float v = U2[t * PP2 + k];
            if (v != 0.f) {
                g_e2[p2] = make_uint2(wx | ((uint32_t)k << 16), __float_as_uint(v));
                ++p2;
            }
        }
    }
    if (t == 0) g_n2 = (unsigned)total2;
}

// b1: zero A accumulator (grid-wide)
__global__ void build_b1()
{
    int i = blockIdx.x * blockDim.x + threadIdx.x;
    if (i < MAXK * NPAD) (&g_Af[0][0])[i] = 0.f;
}

// b2: accumulate A (grid-wide, one thread per U3 element)
__global__ void build_b2(const float* __restrict__ U3)
{
    int i = blockIdx.x * blockDim.x + threadIdx.x;
    if (i >= NU3) return;
    float v = U3[i];
    if (v == 0.f) return;
    int k = i % PP3;
    int r = i / PP3;
    int a = r >> 8, b = (r >> 4) & 15, c = r & 15;
    sort3(a, b, c);
    atomicAdd(&g_Af[g_cellid[a * 256 + b * 16 + c]][k], v);
}

// b3a/b3b: build fragment-major B table (split for ncu launch alignment)
// g_Bf[((c*3 + nt)*2 + rp)*32 + lane] = half2( A[16c+2t4+8rp][n], A[+1][n] )
// with t4 = lane&3, g4 = lane>>2, n = nt*8+g4.
#define BF_WORDS (NCHUNK*3*2*32)   // 11520
#define BF_HALF  (BF_WORDS/2)
__device__ __forceinline__ void bf_fill(int i)
{
    const int lane = i & 31;
    const int rp   = (i >> 5) & 1;
    const int nt   = (i >> 6) % 3;
    const int c    = i / 192;
    const int t4 = lane & 3, g4 = lane >> 2;
    const int k = 16 * c + 2 * t4 + 8 * rp;
    const int n = nt * 8 + g4;
    __half2 h = __floats2half2_rn(g_Af[k][n], g_Af[k + 1][n]);
    g_Bf[i] = *reinterpret_cast<uint32_t*>(&h);
}
__global__ void build_b3a()
{
    int i = blockIdx.x * blockDim.x + threadIdx.x;
    if (i < BF_HALF) bf_fill(i);
}
__global__ void build_b3b()
{
    int i = BF_HALF + blockIdx.x * blockDim.x + threadIdx.x;
    if (i < BF_WORDS) bf_fill(i);
}

// ---------------------------------------------------------------------------
#define MMA16816(d0,d1,d2,d3,a0,a1,a2,a3,b0,b1)                         \
    asm volatile("mma.sync.aligned.m16n8k16.row.col.f32.f16.f16.f32 "   \
        "{%0,%1,%2,%3}, {%4,%5,%6,%7}, {%8,%9}, {%0,%1,%2,%3};"         \
        : "+f"(d0), "+f"(d1), "+f"(d2), "+f"(d3)                        \
        : "r"(a0), "r"(a1), "r"(a2), "r"(a3), "r"(b0), "r"(b1))

__device__ __forceinline__ __half2 u2h2(uint32_t u) { return *reinterpret_cast<__half2*>(&u); }
__device__ __forceinline__ uint32_t h2u(__half2 h) { return *reinterpret_cast<uint32_t*>(&h); }

// ---------------------------------------------------------------------------
// smem layout (bytes), block = 3 nodes x 128 threads
// X 4-replica: row l = 4 replicas x 64 half2 (256B) at replica stride 288B;
// row stride 1152B. Word addr = 288*l + 72*t4 + e  ->  bank = 8*((t4+oct)&3)+g4
// -> all 32 lanes distinct for EVERY x load (r-independent). Conflict-free.
// ---------------------------------------------------------------------------
#define OFF_SPEC  0
#define OFF_NODE  (MAXK * 4)                  // 3840
#define XH_ROW    1152                        // 4 replicas * 288B
#define XH_REP    288
#define W3H_ROW   264                         // 128 fp16 + 8 pad
#define NB_XH     0
#define NB_W3     (NB_XH + LL * XH_ROW)       // 18432
#define NB_W2     (NB_W3 + NPAD * W3H_ROW)    // 24768
#define NB_W1     (NB_W2 + PP2 * 256)         // 25792
#define NB_OUT    (NB_W1 + 512)               // 26304
#define NODE_BYTES (NB_OUT + 512)             // 26816
#define SH_BYTES  (OFF_NODE + NNODES * NODE_BYTES)  // 84288

__global__ __launch_bounds__(THREADS, 2)
void sym_gemm_kernel(const float* __restrict__ x,
                     const float* __restrict__ y,
                     const float* __restrict__ w3,
                     const float* __restrict__ w2,
                     const float* __restrict__ w1,
                     const float* __restrict__ U1,
                     float* __restrict__ out,
                     int B)
{
    extern __shared__ char sm[];
    const int tid  = threadIdx.x;
    const int node = tid >> 7;
    const int wt   = tid & 127;               // channel for setup phases
    const int b    = blockIdx.x * NNODES + node;
    const bool valid = (b < B);

    char* nb  = sm + OFF_NODE + node * NODE_BYTES;
    char* xh  = nb + NB_XH;
    char* w3h = nb + NB_W3;
    char* w2h = nb + NB_W2;
    float* w1f  = reinterpret_cast<float*>(nb + NB_W1);
    float* outs = reinterpret_cast<float*>(nb + NB_OUT);

    const int KP = (int)g_K;
    const int n2 = (int)g_n2;

    // ---- copy spec into smem (all threads) ----
    for (int idx = tid; idx < MAXK; idx += THREADS)
        *reinterpret_cast<uint32_t*>(sm + OFF_SPEC + idx * 4) = g_spec[idx];

    // ---- stage x as PAIRED fp16 into 4 replicas ----
    // entry e = 8*(wt>>4)+(wt&7), half h = (wt>>3)&1
    const int xe = 8 * (wt >> 4) + (wt & 7);
    const int xho = (wt >> 3) & 1;
    if (valid) {
        const float4* xp = reinterpret_cast<const float4*>(x + ((size_t)b * CC + wt) * LL);
#pragma unroll
        for (int q = 0; q < 4; ++q) {
            float4 r = xp[q];
#pragma unroll
            for (int s = 0; s < 4; ++s) {
                const float vv = (s == 0) ? r.x : (s == 1) ? r.y : (s == 2) ? r.z : r.w;
                const __half hv = __float2half(vv);
                char* p = xh + (4 * q + s) * XH_ROW + xe * 4 + xho * 2;
#pragma unroll
                for (int cp = 0; cp < 4; ++cp)
                    *reinterpret_cast<__half*>(p + cp * XH_REP) = hv;
            }
        }
    } else {
#pragma unroll
        for (int l = 0; l < LL; ++l) {
            char* p = xh + l * XH_ROW + xe * 4 + xho * 2;
#pragma unroll
            for (int cp = 0; cp < 4; ++cp)
                *reinterpret_cast<__half*>(p + cp * XH_REP) = __float2half(0.f);
        }
    }

    // ---- effective weights ----
    float yr[EE];
#pragma unroll
    for (int e = 0; e < EE; ++e) yr[e] = valid ? __ldg(y + (size_t)b * EE + e) : 0.f;

#pragma unroll
    for (int k = 0; k < PP3; ++k) {
        float s = 0.f;
#pragma unroll
        for (int e = 0; e < EE; ++e)
            s = fmaf(yr[e], __ldg(w3 + (size_t)(e * PP3 + k) * CC + wt), s);
        *reinterpret_cast<__half*>(w3h + k * W3H_ROW + wt * 2) = __float2half(s);
    }
    *reinterpret_cast<__half*>(w3h + 23 * W3H_ROW + wt * 2) = __float2half(0.f);  // pad col
#pragma unroll
    for (int k = 0; k < PP2; ++k) {
        float s = 0.f;
#pragma unroll
        for (int e = 0; e < EE; ++e)
            s = fmaf(yr[e], __ldg(w2 + (size_t)(e * PP2 + k) * CC + wt), s);
        *reinterpret_cast<__half*>(w2h + k * 256 + wt * 2) = __float2half(s);
    }
    {
        float s = 0.f;
#pragma unroll
        for (int e = 0; e < EE; ++e)
            s = fmaf(yr[e], __ldg(w1 + (size_t)e * CC + wt), s);
        w1f[wt] = s;
    }
    __syncthreads();   // x (written by other threads' channels) + tables ready

    // ---- U2 + U1 scalar terms for channel wt (replica 0) ----
    {
        float o = 0.f;
        for (int e = 0; e < n2; ++e) {
            uint2 E = __ldg(&g_e2[e]);
            const int ww = E.x & 255, xx = (E.x >> 8) & 255, kk = E.x >> 16;
            float xw = __half2float(*reinterpret_cast<const __half*>(xh + ww * XH_ROW + xe * 4 + xho * 2))
                     * __half2float(*reinterpret_cast<const __half*>(xh + xx * XH_ROW + xe * 4 + xho * 2));
            float wv = __half2float(*reinterpret_cast<const __half*>(w2h + kk * 256 + wt * 2));
            o = fmaf(__uint_as_float(E.y) * wv, xw, o);
        }
        float d = 0.f;
#pragma unroll
        for (int l = 0; l < LL; ++l)
            d = fmaf(__ldg(U1 + l),
                     __half2float(*reinterpret_cast<const __half*>(xh + l * XH_ROW + xe * 4 + xho * 2)), d);
        o = fmaf(w1f[wt], d, o);
        outs[wt] = o;
    }

    // ---- GEMM main loop: barrier-free, conflict-free x-gather ----
    const int lane = tid & 31;
    const int wm   = (tid >> 5) & 3;          // warp within node
    const int g4   = lane >> 2;
    const int t4   = lane & 3;

    // per-lane x base for each m-tile (own replica): entry = 8*(2wm+mt)+g4
    const char* xc0 = xh + t4 * XH_REP + (8 * (2 * wm + 0) + g4) * 4;
    const char* xc1 = xh + t4 * XH_REP + (8 * (2 * wm + 1) + g4) * 4;
    const uint2* spec2 = reinterpret_cast<const uint2*>(sm + OFF_SPEC);
    const uint32_t* bf = g_Bf + lane;

    float acc[2][3][4];
#pragma unroll
    for (int mt = 0; mt < 2; ++mt)
#pragma unroll
        for (int nt = 0; nt < 3; ++nt)
#pragma unroll
            for (int q = 0; q < 4; ++q) acc[mt][nt][q] = 0.f;

    const int nchunks = KP >> 4;
    for (int c = 0; c < nchunks; ++c) {
        // spec pairs for cols (2t4, 2t4+1) and (2t4+8, 2t4+9)
        uint2 spJ0 = spec2[8 * c + t4];
        uint2 spJ1 = spec2[8 * c + t4 + 4];

        uint32_t afr[2][4];
#pragma unroll
        for (int mt = 0; mt < 2; ++mt) {
            const char* xc = mt ? xc1 : xc0;
#pragma unroll
            for (int j = 0; j < 2; ++j) {
                const uint32_t spA = j ? spJ1.x : spJ0.x;
                const uint32_t spB = j ? spJ1.y : spJ0.y;
                __half2 xa = u2h2(*reinterpret_cast<const uint32_t*>(xc + (spA & 255u) * XH_ROW));
                __half2 xb = u2h2(*reinterpret_cast<const uint32_t*>(xc + ((spA >> 8) & 255u) * XH_ROW));
                __half2 c0 = u2h2(*reinterpret_cast<const uint32_t*>(xc + ((spA >> 16) & 255u) * XH_ROW));
                __half2 c1 = u2h2(*reinterpret_cast<const uint32_t*>(xc + ((spB >> 16) & 255u) * XH_ROW));
                __half2 ab = __hmul2(xa, xb);
                uint32_t p0 = h2u(__hmul2(ab, c0));   // (row g4, row g4+8) @ col k0
                uint32_t p1 = h2u(__hmul2(ab, c1));   // (row g4, row g4+8) @ col k1
                afr[mt][2 * j + 0] = __byte_perm(p0, p1, 0x5410);  // row g4:   (k0,k1)
                afr[mt][2 * j + 1] = __byte_perm(p0, p1, 0x7632);  // row g4+8: (k0,k1)
            }
        }

        // B fragments (coalesced L1-resident LDG) + mma
        const uint32_t* bc = bf + c * 192;
#pragma unroll
        for (int nt = 0; nt < 3; ++nt) {
            uint32_t b0 = __ldg(bc + nt * 64);
            uint32_t b1 = __ldg(bc + nt * 64 + 32);
            MMA16816(acc[0][nt][0], acc[0][nt][1], acc[0][nt][2], acc[0][nt][3],
                     afr[0][0], afr[0][1], afr[0][2], afr[0][3], b0, b1);
            MMA16816(acc[1][nt][0], acc[1][nt][1], acc[1][nt][2], acc[1][nt][3],
                     afr[1][0], afr[1][1], afr[1][2], afr[1][3], b0, b1);
        }
    }

    // ---- epilogue: out[ch] = outs[ch] + sum_k W3[k][ch] * Q[ch][k] ----
#pragma unroll
    for (int mt = 0; mt < 2; ++mt) {
#pragma unroll
        for (int h = 0; h < 2; ++h) {
            const int ch = wm * 32 + mt * 16 + g4 + h * 8;
            float S = 0.f;
#pragma unroll
            for (int nt = 0; nt < 3; ++nt) {
                const int k0 = nt * 8 + 2 * t4;
                float wv0 = __half2float(*reinterpret_cast<const __half*>(w3h + k0 * W3H_ROW + ch * 2));
                float wv1 = __half2float(*reinterpret_cast<const __half*>(w3h + (k0 + 1) * W3H_ROW + ch * 2));
                S = fmaf(acc[mt][nt][h * 2 + 0], wv0, S);
                S = fmaf(acc[mt][nt][h * 2 + 1], wv1, S);
            }
            S += __shfl_xor_sync(0xffffffffu, S, 1);
            S += __shfl_xor_sync(0xffffffffu, S, 2);
            if (t4 == 0 && valid)
                out[(size_t)b * CC + ch] = S + outs[ch];
        }
    }
}

// ---------------------------------------------------------------------------
extern "C" void kernel_launch(void* const* d_in, const int* in_sizes, int n_in,
                              void* d_out, int out_size)
{
    const float* x  = (const float*)d_in[0];   // [B,C,L]
    const float* y  = (const float*)d_in[1];   // [B,E]
    const float* U3 = (const float*)d_in[2];   // [16,16,16,23]
    const float* U2 = (const float*)d_in[3];   // [16,16,4]
    const float* U1 = (const float*)d_in[4];   // [16,1]
    const float* w3 = (const float*)d_in[5];   // [10,23,128]
    const float* w2 = (const float*)d_in[6];   // [10,4,128]
    const float* w1 = (const float*)d_in[7];   // [10,1,128]
    float* out = (float*)d_out;

    const int B = in_sizes[0] / (CC * LL);

    build_b0<<<1, 1024>>>(U3, U2);
    build_b1<<<(MAXK * NPAD + 255) / 256, 256>>>();
    build_b2<<<(NU3 + 255) / 256, 256>>>(U3);
    build_b3a<<<(BF_HALF + 255) / 256, 256>>>();
    build_b3b<<<(BF_HALF + 255) / 256, 256>>>();

    cudaFuncSetAttribute(sym_gemm_kernel,
                         cudaFuncAttributeMaxDynamicSharedMemorySize, SH_BYTES);
    const int grid = (B + NNODES - 1) / NNODES;
    sym_gemm_kernel<<<grid, THREADS, SH_BYTES>>>(x, y, w3, w2, w1, U1, out, B);
}

// round 17
// speedup vs baseline: 1.1606x; 1.0240x over previous
#include <cuda_runtime.h>
#include <cuda_fp16.h>
#include <cstdint>

// ---------------------------------------------------------------------------
// SymmetricContraction via monomial GEMM (fp16 in / fp32 accum mma.m16n8k16).
// out[b,c] = sum_k W3[k]*Q3[k] + U2/U1 scalar terms
//   Q3[b,c,k] = sum_T A[T,k] * m[b,c,T],  m = x_a x_b x_c over sorted triples
// Pair-even runs (K<=960). 4-replica mt-interleaved X (conflict-free LDS.64
// x-gather, both m-tiles per load). B fragment-major in global (L1-hot).
// Software-pipelined spec/B prefetch; barrier-free main loop.
// ---------------------------------------------------------------------------

#define CC   128
#define LL   16
#define EE   10
#define PP3  23
#define PP2  4
#define NU3  (16*16*16*23)   // 94208
#define MAXK 960             // sorted triples + pair padding (bound 952)
#define NCHUNK (MAXK/16)     // 60
#define NPAD 24              // GEMM N: 23 paths + 1 zero col
#define NNODES 3
#define THREADS (NNODES*128)

// ---- device globals (no allocation allowed) ----
__device__ float          g_Af[MAXK][NPAD];        // fp32 A accumulation
__device__ uint32_t       g_Bf[NCHUNK*192 + 192];  // fragment-major B (+pad)
__device__ uint32_t       g_spec[MAXK + 16];       // a|b<<8|c<<16 (+pad)
__device__ unsigned short g_cellid[4096];          // sorted-cell -> slot
__device__ uint2          g_e2[1040];              // U2: (w|x<<8|k<<16, f32 v)
__device__ unsigned       g_K;                     // padded K
__device__ unsigned       g_n2;

// ---------------------------------------------------------------------------
__device__ __forceinline__ int block_exscan_1024(int cnt, int t, int* warp_sums, int* total)
{
    __syncthreads();
    const int lane = t & 31, wid = t >> 5;
    int inc = cnt;
#pragma unroll
    for (int d = 1; d < 32; d <<= 1) {
        int n = __shfl_up_sync(0xffffffffu, inc, d);
        if (lane >= d) inc += n;
    }
    if (lane == 31) warp_sums[wid] = inc;
    __syncthreads();
    if (wid == 0) {
        int v = warp_sums[lane];
#pragma unroll
        for (int d = 1; d < 32; d <<= 1) {
            int n = __shfl_up_sync(0xffffffffu, v, d);
            if (lane >= d) v += n;
        }
        warp_sums[lane] = v;
    }
    __syncthreads();
    *total = warp_sums[31];
    return inc - cnt + (wid ? warp_sums[wid - 1] : 0);
}

__device__ __forceinline__ void sort3(int& a, int& b, int& c)
{
    int t;
    if (a > b) { t = a; a = b; b = t; }
    if (b > c) { t = b; b = c; c = t; }
    if (a > b) { t = a; a = b; b = t; }
}

// ---------------------------------------------------------------------------
// b0: single block. used3 bitmap -> pair-even slotting -> spec/cellid. U2 list.
// ---------------------------------------------------------------------------
__global__ __launch_bounds__(1024)
void build_b0(const float* __restrict__ U3, const float* __restrict__ U2)
{
    __shared__ int           warp_sums[32];
    __shared__ unsigned char used3[4096];
    const int t = threadIdx.x;

    for (int idx = t; idx < MAXK + 16; idx += 1024) g_spec[idx] = 0u;
#pragma unroll
    for (int j = 0; j < 4; ++j) used3[t * 4 + j] = 0;
    __syncthreads();

    const int base = t * 92;
    const int w  = t >> 6;
    const int x2 = (t >> 2) & 15;
#pragma unroll
    for (int g = 0; g < 4; ++g) {
        const int i = (t & 3) * 4 + g;
        for (int k = 0; k < PP3; ++k) {
            if (U3[base + g * PP3 + k] != 0.f) {
                int a = w, b = x2, c = i;
                sort3(a, b, c);
                used3[a * 256 + b * 16 + c] = 1;
            }
        }
    }
    __syncthreads();

    // pair-even slotting: pair (a,b) with a<=b owns even # of slots
    int a = t >> 4, b = t & 15;
    int cnt = 0;
    if (t < 256 && a <= b)
        for (int c = b; c < 16; ++c) cnt += used3[a * 256 + b * 16 + c];
    int slots = (cnt + 1) & ~1;
    int total;
    int basep = block_exscan_1024((t < 256) ? slots : 0, t, warp_sums, &total);
    if (t < 256 && cnt > 0) {
        int pos = basep;
        for (int c = b; c < 16; ++c) {
            const int cell = a * 256 + b * 16 + c;
            if (used3[cell]) {
                g_cellid[cell] = (unsigned short)pos;
                g_spec[pos] = (uint32_t)a | ((uint32_t)b << 8) | ((uint32_t)c << 16);
                ++pos;
            }
        }
        if (cnt & 1)   // dummy slot: same (a,b), A row stays zero
            g_spec[pos] = (uint32_t)a | ((uint32_t)b << 8) | (15u << 16);
    }
    if (t == 0) g_K = (unsigned)((total + 15) & ~15);

    // ---- U2 list ----
    int cnt2 = 0;
    if (t < 256) {
#pragma unroll
        for (int k = 0; k < PP2; ++k) cnt2 += (U2[t * PP2 + k] != 0.f);
    }
    int total2;
    int p2 = block_exscan_1024(cnt2, t, warp_sums, &total2);
    if (t < 256) {
        const uint32_t wx = (uint32_t)(t >> 4) | ((uint32_t)(t & 15) << 8);
        for (int k = 0; k < PP2; ++k) {
            float v = U2[t * PP2 + k];
            if (v != 0.f) {
                g_e2[p2] = make_uint2(wx | ((uint32_t)k << 16), __float_as_uint(v));
                ++p2;
            }
        }
    }
    if (t == 0) g_n2 = (unsigned)total2;
}

// b1: zero A accumulator (grid-wide)
__global__ void build_b1()
{
    int i = blockIdx.x * blockDim.x + threadIdx.x;
    if (i < MAXK * NPAD) (&g_Af[0][0])[i] = 0.f;
}

// b2: accumulate A (grid-wide, one thread per U3 element)
__global__ void build_b2(const float* __restrict__ U3)
{
    int i = blockIdx.x * blockDim.x + threadIdx.x;
    if (i >= NU3) return;
    float v = U3[i];
    if (v == 0.f) return;
    int k = i % PP3;
    int r = i / PP3;
    int a = r >> 8, b = (r >> 4) & 15, c = r & 15;
    sort3(a, b, c);
    atomicAdd(&g_Af[g_cellid[a * 256 + b * 16 + c]][k], v);
}

// b3a/b3b: fragment-major B table
// g_Bf[((c*3 + nt)*2 + rp)*32 + lane] = half2( A[16c+2t4+8rp][n], A[+1][n] )
#define BF_WORDS (NCHUNK*192)   // 11520
#define BF_HALF  (BF_WORDS/2)
__device__ __forceinline__ void bf_fill(int i)
{
    const int lane = i & 31;
    const int rp   = (i >> 5) & 1;
    const int nt   = (i >> 6) % 3;
    const int c    = i / 192;
    const int t4 = lane & 3, g4 = lane >> 2;
    const int k = 16 * c + 2 * t4 + 8 * rp;
    const int n = nt * 8 + g4;
    __half2 h = __floats2half2_rn(g_Af[k][n], g_Af[k + 1][n]);
    g_Bf[i] = *reinterpret_cast<uint32_t*>(&h);
}
__global__ void build_b3a()
{
    int i = blockIdx.x * blockDim.x + threadIdx.x;
    if (i < BF_HALF) bf_fill(i);
}
__global__ void build_b3b()
{
    int i = BF_HALF + blockIdx.x * blockDim.x + threadIdx.x;
    if (i < BF_WORDS) bf_fill(i);
    // zero the prefetch pad
    int j = blockIdx.x * blockDim.x + threadIdx.x;
    if (j < 192) g_Bf[BF_WORDS + j] = 0u;
}

// ---------------------------------------------------------------------------
#define MMA16816(d0,d1,d2,d3,a0,a1,a2,a3,b0,b1)                         \
    asm volatile("mma.sync.aligned.m16n8k16.row.col.f32.f16.f16.f32 "   \
        "{%0,%1,%2,%3}, {%4,%5,%6,%7}, {%8,%9}, {%0,%1,%2,%3};"         \
        : "+f"(d0), "+f"(d1), "+f"(d2), "+f"(d3)                        \
        : "r"(a0), "r"(a1), "r"(a2), "r"(a3), "r"(b0), "r"(b1))

__device__ __forceinline__ __half2 u2h2(uint32_t u) { return *reinterpret_cast<__half2*>(&u); }
__device__ __forceinline__ uint32_t h2u(__half2 h) { return *reinterpret_cast<uint32_t*>(&h); }

// ---------------------------------------------------------------------------
// smem layout (bytes), block = 3 nodes x 128 threads
// X 4-replica mt-interleaved: replica word w = 16*wm + 2*g4 + mt holds
// half2(x[ch], x[ch+8]) for ch = 32*wm + 16*mt + g4 (+8 in .hi).
// Replica stride 288B, row stride 1152B. LDS.64 at (16wm+2g4) words loads
// both mt values; two-phase banks 8t4+2g4 distinct per half-warp.
// ---------------------------------------------------------------------------
#define OFF_SPEC  0
#define OFF_NODE  ((MAXK + 16) * 4)           // 3904
#define XH_ROW    1152                        // 4 replicas * 288B
#define XH_REP    288
#define W3H_ROW   264                         // 128 fp16 + 8 pad
#define NB_XH     0
#define NB_W3     (NB_XH + LL * XH_ROW)       // 18432
#define NB_W2     (NB_W3 + NPAD * W3H_ROW)    // 24768
#define NB_W1     (NB_W2 + PP2 * 256)         // 25792
#define NB_OUT    (NB_W1 + 512)               // 26304
#define NODE_BYTES (NB_OUT + 512)             // 26816
#define SH_BYTES  (OFF_NODE + NNODES * NODE_BYTES)  // 84352

__global__ __launch_bounds__(THREADS, 2)
void sym_gemm_kernel(const float* __restrict__ x,
                     const float* __restrict__ y,
                     const float* __restrict__ w3,
                     const float* __restrict__ w2,
                     const float* __restrict__ w1,
                     const float* __restrict__ U1,
                     float* __restrict__ out,
                     int B)
{
    extern __shared__ char sm[];
    const int tid  = threadIdx.x;
    const int node = tid >> 7;
    const int wt   = tid & 127;               // channel for setup phases
    const int b    = blockIdx.x * NNODES + node;
    const bool valid = (b < B);

    char* nb  = sm + OFF_NODE + node * NODE_BYTES;
    char* xh  = nb + NB_XH;
    char* w3h = nb + NB_W3;
    char* w2h = nb + NB_W2;
    float* w1f  = reinterpret_cast<float*>(nb + NB_W1);
    float* outs = reinterpret_cast<float*>(nb + NB_OUT);

    const int KP = (int)g_K;
    const int n2 = (int)g_n2;

    // ---- copy spec (incl. pad) into smem ----
    for (int idx = tid; idx < MAXK + 16; idx += THREADS)
        *reinterpret_cast<uint32_t*>(sm + OFF_SPEC + idx * 4) = g_spec[idx];

    // ---- stage x as PAIRED fp16 into 4 replicas, mt-interleaved words ----
    // channel wt: q = wt>>4 (block of 16), r = wt&7, h = (wt>>3)&1
    // word = 16*(q>>1) + 2*r + (q&1); half2 holds (ch, ch+8)
    const int xq = wt >> 4;
    const int xword = 16 * (xq >> 1) + 2 * (wt & 7) + (xq & 1);
    const int xho = (wt >> 3) & 1;
    const int xoff = xword * 4 + xho * 2;
    if (valid) {
        const float4* xp = reinterpret_cast<const float4*>(x + ((size_t)b * CC + wt) * LL);
#pragma unroll
        for (int q = 0; q < 4; ++q) {
            float4 r = xp[q];
#pragma unroll
            for (int s = 0; s < 4; ++s) {
                const float vv = (s == 0) ? r.x : (s == 1) ? r.y : (s == 2) ? r.z : r.w;
                const __half hv = __float2half(vv);
                char* p = xh + (4 * q + s) * XH_ROW + xoff;
#pragma unroll
                for (int cp = 0; cp < 4; ++cp)
                    *reinterpret_cast<__half*>(p + cp * XH_REP) = hv;
            }
        }
    } else {
#pragma unroll
        for (int l = 0; l < LL; ++l) {
            char* p = xh + l * XH_ROW + xoff;
#pragma unroll
            for (int cp = 0; cp < 4; ++cp)
                *reinterpret_cast<__half*>(p + cp * XH_REP) = __float2half(0.f);
        }
    }

    // ---- effective weights ----
    float yr[EE];
#pragma unroll
    for (int e = 0; e < EE; ++e) yr[e] = valid ? __ldg(y + (size_t)b * EE + e) : 0.f;

#pragma unroll
    for (int k = 0; k < PP3; ++k) {
        float s = 0.f;
#pragma unroll
        for (int e = 0; e < EE; ++e)
            s = fmaf(yr[e], __ldg(w3 + (size_t)(e * PP3 + k) * CC + wt), s);
        *reinterpret_cast<__half*>(w3h + k * W3H_ROW + wt * 2) = __float2half(s);
    }
    *reinterpret_cast<__half*>(w3h + 23 * W3H_ROW + wt * 2) = __float2half(0.f);  // pad col
#pragma unroll
    for (int k = 0; k < PP2; ++k) {
        float s = 0.f;
#pragma unroll
        for (int e = 0; e < EE; ++e)
            s = fmaf(yr[e], __ldg(w2 + (size_t)(e * PP2 + k) * CC + wt), s);
        *reinterpret_cast<__half*>(w2h + k * 256 + wt * 2) = __float2half(s);
    }
    {
        float s = 0.f;
#pragma unroll
        for (int e = 0; e < EE; ++e)
            s = fmaf(yr[e], __ldg(w1 + (size_t)e * CC + wt), s);
        w1f[wt] = s;
    }
    __syncthreads();   // x (written by other threads' channels) + tables ready

    // ---- U2 + U1 scalar terms for channel wt (replica 0) ----
    {
        float o = 0.f;
        for (int e = 0; e < n2; ++e) {
            uint2 E = __ldg(&g_e2[e]);
            const int ww = E.x & 255, xx = (E.x >> 8) & 255, kk = E.x >> 16;
            float xw = __half2float(*reinterpret_cast<const __half*>(xh + ww * XH_ROW + xoff))
                     * __half2float(*reinterpret_cast<const __half*>(xh + xx * XH_ROW + xoff));
            float wv = __half2float(*reinterpret_cast<const __half*>(w2h + kk * 256 + wt * 2));
            o = fmaf(__uint_as_float(E.y) * wv, xw, o);
        }
        float d = 0.f;
#pragma unroll
        for (int l = 0; l < LL; ++l)
            d = fmaf(__ldg(U1 + l),
                     __half2float(*reinterpret_cast<const __half*>(xh + l * XH_ROW + xoff)), d);
        o = fmaf(w1f[wt], d, o);
        outs[wt] = o;
    }

    // ---- GEMM main loop: barrier-free, prefetch depth 1 ----
    const int lane = tid & 31;
    const int wm   = (tid >> 5) & 3;          // warp within node
    const int g4   = lane >> 2;
    const int t4   = lane & 3;

    // x base: LDS.64 at word 16*wm+2*g4 gives half2 for mt=0 (.x) and mt=1 (.y)
    const char* xcb = xh + t4 * XH_REP + (16 * wm + 2 * g4) * 4;
    const uint2* spec2 = reinterpret_cast<const uint2*>(sm + OFF_SPEC);
    const uint32_t* bf = g_Bf + lane;

    float acc[2][3][4];
#pragma unroll
    for (int mt = 0; mt < 2; ++mt)
#pragma unroll
        for (int nt = 0; nt < 3; ++nt)
#pragma unroll
            for (int q = 0; q < 4; ++q) acc[mt][nt][q] = 0.f;

    const int nchunks = KP >> 4;

    // prefetch chunk 0
    uint2 sN0 = spec2[t4];
    uint2 sN1 = spec2[t4 + 4];
    uint32_t bN[6];
#pragma unroll
    for (int nt = 0; nt < 3; ++nt) {
        bN[2 * nt]     = __ldg(bf + nt * 64);
        bN[2 * nt + 1] = __ldg(bf + nt * 64 + 32);
    }

#pragma unroll 2
    for (int c = 0; c < nchunks; ++c) {
        const uint2 spJ0 = sN0, spJ1 = sN1;
        uint32_t bC[6];
#pragma unroll
        for (int q = 0; q < 6; ++q) bC[q] = bN[q];

        // prefetch chunk c+1 (pads guarantee in-bounds; values unused at end)
        sN0 = spec2[8 * (c + 1) + t4];
        sN1 = spec2[8 * (c + 1) + t4 + 4];
        const uint32_t* bn = bf + (c + 1) * 192;
#pragma unroll
        for (int nt = 0; nt < 3; ++nt) {
            bN[2 * nt]     = __ldg(bn + nt * 64);
            bN[2 * nt + 1] = __ldg(bn + nt * 64 + 32);
        }

        // A fragments: LDS.64 loads both m-tiles at once
        uint32_t afr[2][4];
#pragma unroll
        for (int j = 0; j < 2; ++j) {
            const uint32_t spA = j ? spJ1.x : spJ0.x;
            const uint32_t spB = j ? spJ1.y : spJ0.y;
            uint2 xa = *reinterpret_cast<const uint2*>(xcb + (spA & 255u) * XH_ROW);
            uint2 xb = *reinterpret_cast<const uint2*>(xcb + ((spA >> 8) & 255u) * XH_ROW);
            uint2 c0 = *reinterpret_cast<const uint2*>(xcb + ((spA >> 16) & 255u) * XH_ROW);
            uint2 c1 = *reinterpret_cast<const uint2*>(xcb + ((spB >> 16) & 255u) * XH_ROW);
            __half2 ab0 = __hmul2(u2h2(xa.x), u2h2(xb.x));   // mt=0
            __half2 ab1 = __hmul2(u2h2(xa.y), u2h2(xb.y));   // mt=1
            uint32_t p0m0 = h2u(__hmul2(ab0, u2h2(c0.x)));
            uint32_t p1m0 = h2u(__hmul2(ab0, u2h2(c1.x)));
            uint32_t p0m1 = h2u(__hmul2(ab1, u2h2(c0.y)));
            uint32_t p1m1 = h2u(__hmul2(ab1, u2h2(c1.y)));
            afr[0][2 * j + 0] = __byte_perm(p0m0, p1m0, 0x5410);
            afr[0][2 * j + 1] = __byte_perm(p0m0, p1m0, 0x7632);
            afr[1][2 * j + 0] = __byte_perm(p0m1, p1m1, 0x5410);
            afr[1][2 * j + 1] = __byte_perm(p0m1, p1m1, 0x7632);
        }

        // MMAs with current B
#pragma unroll
        for (int nt = 0; nt < 3; ++nt) {
            MMA16816(acc[0][nt][0], acc[0][nt][1], acc[0][nt][2], acc[0][nt][3],
                     afr[0][0], afr[0][1], afr[0][2], afr[0][3], bC[2 * nt], bC[2 * nt + 1]);
            MMA16816(acc[1][nt][0], acc[1][nt][1], acc[1][nt][2], acc[1][nt][3],
                     afr[1][0], afr[1][1], afr[1][2], afr[1][3], bC[2 * nt], bC[2 * nt + 1]);
        }
    }

    // ---- epilogue: out[ch] = outs[ch] + sum_k W3[k][ch] * Q[ch][k] ----
    // fragment row of acc[mt]: ch = 32*wm + 16*mt + g4 + 8*h (matches X pairing)
#pragma unroll
    for (int mt = 0; mt < 2; ++mt) {
#pragma unroll
        for (int h = 0; h < 2; ++h) {
            const int ch = wm * 32 + mt * 16 + g4 + h * 8;
            float S = 0.f;
#pragma unroll
            for (int nt = 0; nt < 3; ++nt) {
                const int k0 = nt * 8 + 2 * t4;
                float wv0 = __half2float(*reinterpret_cast<const __half*>(w3h + k0 * W3H_ROW + ch * 2));
                float wv1 = __half2float(*reinterpret_cast<const __half*>(w3h + (k0 + 1) * W3H_ROW + ch * 2));
                S = fmaf(acc[mt][nt][h * 2 + 0], wv0, S);
                S = fmaf(acc[mt][nt][h * 2 + 1], wv1, S);
            }
            S += __shfl_xor_sync(0xffffffffu, S, 1);
            S += __shfl_xor_sync(0xffffffffu, S, 2);
            if (t4 == 0 && valid)
                out[(size_t)b * CC + ch] = S + outs[ch];
        }
    }
}

// ---------------------------------------------------------------------------
extern "C" void kernel_launch(void* const* d_in, const int* in_sizes, int n_in,
                              void* d_out, int out_size)
{
    const float* x  = (const float*)d_in[0];   // [B,C,L]
    const float* y  = (const float*)d_in[1];   // [B,E]
    const float* U3 = (const float*)d_in[2];   // [16,16,16,23]
    const float* U2 = (const float*)d_in[3];   // [16,16,4]
    const float* U1 = (const float*)d_in[4];   // [16,1]
    const float* w3 = (const float*)d_in[5];   // [10,23,128]
    const float* w2 = (const float*)d_in[6];   // [10,4,128]
    const float* w1 = (const float*)d_in[7];   // [10,1,128]
    float* out = (float*)d_out;

    const int B = in_sizes[0] / (CC * LL);

    build_b0<<<1, 1024>>>(U3, U2);
    build_b1<<<(MAXK * NPAD + 255) / 256, 256>>>();
    build_b2<<<(NU3 + 255) / 256, 256>>>(U3);
    build_b3a<<<(BF_HALF + 255) / 256, 256>>>();
    build_b3b<<<(BF_HALF + 255) / 256, 256>>>();

    cudaFuncSetAttribute(sym_gemm_kernel,
                         cudaFuncAttributeMaxDynamicSharedMemorySize, SH_BYTES);
    const int grid = (B + NNODES - 1) / NNODES;
    sym_gemm_kernel<<<grid, THREADS, SH_BYTES>>>(x, y, w3, w2, w1, U1, out, B);
}